// round 2
// baseline (speedup 1.0000x reference)
#include <cuda_runtime.h>
#include <cuda_bf16.h>
#include <math.h>

// Problem constants (fixed by the reference)
#define BB 2048   // batch
#define TT 80     // time steps
#define EE 100    // embed dim
#define UU 512    // hidden dim

// GEMM tiling
#define BM 64
#define BN 64
#define BK 16

// Ping-pong hidden-state scratch (no allocations allowed -> __device__ globals)
__device__ float g_H[2][BB * UU];

// One recurrence step:
//   Hout = tanh( emb[x[:,t]] @ Wx1 + Hin @ Wh1 + b1 )
// skip_h == 1 on the first step (Hin == 0) to skip the 512-K loop.
__global__ __launch_bounds__(256) void step_kernel(
    const int*   __restrict__ x,     // [B, T] int32 tokens
    const float* __restrict__ emb,   // [V, E]
    const float* __restrict__ Wx,    // [E, U]
    const float* __restrict__ Wh,    // [U, U]
    const float* __restrict__ b1,    // [U]
    int t, int src, int dst, int skip_h)
{
    __shared__ float As[BK][BM];
    __shared__ float Bs[BK][BN];
    __shared__ int   toks[BM];

    const int tid = threadIdx.x;
    const int tx  = tid & 15;        // 0..15 -> output cols (x4)
    const int ty  = tid >> 4;        // 0..15 -> output rows (x4)
    const int row0 = blockIdx.y * BM;
    const int col0 = blockIdx.x * BN;

    const float* __restrict__ Hin  = g_H[src];
    float*       __restrict__ Hout = g_H[dst];

    // Load the 64 token ids for this row-tile.
    if (tid < BM) toks[tid] = x[(row0 + tid) * TT + t];
    __syncthreads();

    float acc[4][4] = {};

    // A-tile loader mapping: each thread loads one float4 of A (transposed store)
    const int lm  = tid >> 2;        // 0..63  : m within tile
    const int lkq = tid & 3;         // 0..3   : k quad (k = lkq*4 .. +3)
    // B-tile loader mapping: each thread loads one float4 of B
    const int lk  = tid >> 4;        // 0..15  : k within tile
    const int lnq = tid & 15;        // 0..15  : n quad (n = lnq*4)

    // ---- Part 1: Hin @ Wh1 (K = 512) ----
    if (!skip_h) {
        for (int k0 = 0; k0 < UU; k0 += BK) {
            float4 av = *(const float4*)&Hin[(row0 + lm) * UU + k0 + lkq * 4];
            float4 bv = *(const float4*)&Wh[(k0 + lk) * UU + col0 + lnq * 4];
            __syncthreads();  // previous tile's compute done before overwrite
            As[lkq * 4 + 0][lm] = av.x;
            As[lkq * 4 + 1][lm] = av.y;
            As[lkq * 4 + 2][lm] = av.z;
            As[lkq * 4 + 3][lm] = av.w;
            *(float4*)&Bs[lk][lnq * 4] = bv;
            __syncthreads();
            #pragma unroll
            for (int k = 0; k < BK; k++) {
                float4 a = *(const float4*)&As[k][ty * 4];
                float4 b = *(const float4*)&Bs[k][tx * 4];
                float  ar[4] = {a.x, a.y, a.z, a.w};
                float  br[4] = {b.x, b.y, b.z, b.w};
                #pragma unroll
                for (int i = 0; i < 4; i++)
                    #pragma unroll
                    for (int j = 0; j < 4; j++)
                        acc[i][j] += ar[i] * br[j];
            }
        }
    }

    // ---- Part 2: emb[tok] @ Wx1 (K = 100, padded to 112) ----
    for (int k0 = 0; k0 < 112; k0 += BK) {
        int ea = k0 + lkq * 4;   // A-side e index (float4 start)
        float4 av = (ea < EE) ? *(const float4*)&emb[toks[lm] * EE + ea]
                              : make_float4(0.f, 0.f, 0.f, 0.f);
        int eb = k0 + lk;        // B-side e row
        float4 bv = (eb < EE) ? *(const float4*)&Wx[eb * UU + col0 + lnq * 4]
                              : make_float4(0.f, 0.f, 0.f, 0.f);
        __syncthreads();
        As[lkq * 4 + 0][lm] = av.x;
        As[lkq * 4 + 1][lm] = av.y;
        As[lkq * 4 + 2][lm] = av.z;
        As[lkq * 4 + 3][lm] = av.w;
        *(float4*)&Bs[lk][lnq * 4] = bv;
        __syncthreads();
        #pragma unroll
        for (int k = 0; k < BK; k++) {
            float4 a = *(const float4*)&As[k][ty * 4];
            float4 b = *(const float4*)&Bs[k][tx * 4];
            float  ar[4] = {a.x, a.y, a.z, a.w};
            float  br[4] = {b.x, b.y, b.z, b.w};
            #pragma unroll
            for (int i = 0; i < 4; i++)
                #pragma unroll
                for (int j = 0; j < 4; j++)
                    acc[i][j] += ar[i] * br[j];
        }
    }

    // ---- Epilogue: bias + tanh ----
    #pragma unroll
    for (int i = 0; i < 4; i++) {
        int r = row0 + ty * 4 + i;
        #pragma unroll
        for (int j = 0; j < 4; j++) {
            int c = col0 + tx * 4 + j;
            Hout[r * UU + c] = tanhf(acc[i][j] + b1[c]);
        }
    }
}

// out[b] = sigmoid( dot(H[b,:], Wout) + bout )
__global__ __launch_bounds__(256) void out_kernel(
    const float* __restrict__ Wout,  // [U, 1]
    const float* __restrict__ bout,  // [1]
    float* __restrict__ out,         // [B, 1]
    int final_buf)
{
    int gwarp = (blockIdx.x * blockDim.x + threadIdx.x) >> 5;
    int lane  = threadIdx.x & 31;
    if (gwarp >= BB) return;
    const float* h = &g_H[final_buf][gwarp * UU];
    float s = 0.f;
    #pragma unroll
    for (int k = lane; k < UU; k += 32) s += h[k] * Wout[k];
    #pragma unroll
    for (int o = 16; o; o >>= 1) s += __shfl_xor_sync(0xFFFFFFFFu, s, o);
    if (lane == 0) out[gwarp] = 1.f / (1.f + expf(-(s + bout[0])));
}

extern "C" void kernel_launch(void* const* d_in, const int* in_sizes, int n_in,
                              void* d_out, int out_size)
{
    (void)in_sizes; (void)n_in; (void)out_size;
    // metadata order: x, emb, Wx0, Wh0, b0, Wx1, Wh1, b1, Wout, bout
    const int*   x    = (const int*)  d_in[0];
    const float* emb  = (const float*)d_in[1];
    // d_in[2..4] (Wx0, Wh0, b0) are dead: h0 never reaches the output.
    const float* Wx1  = (const float*)d_in[5];
    const float* Wh1  = (const float*)d_in[6];
    const float* b1   = (const float*)d_in[7];
    const float* Wout = (const float*)d_in[8];
    const float* bout = (const float*)d_in[9];
    float* out = (float*)d_out;

    dim3 grid(UU / BN, BB / BM);   // (8, 32) = 256 CTAs
    for (int t = 0; t < TT; t++) {
        int src = t & 1;
        int dst = (t + 1) & 1;
        step_kernel<<<grid, 256>>>(x, emb, Wx1, Wh1, b1, t, src, dst, (t == 0) ? 1 : 0);
    }
    // After t = 79, result lives in buffer (80 & 1) == 0.
    out_kernel<<<BB / 8, 256>>>(Wout, bout, out, 0);
}

// round 4
// speedup vs baseline: 2.9683x; 2.9683x over previous
#include <cuda_runtime.h>
#include <cuda_bf16.h>
#include <math.h>
#include <stdint.h>

// ---------------- problem constants ----------------
#define BB 2048     // batch
#define TT 80       // time steps
#define EE 100      // embed dim
#define VV 10000    // vocab
#define UU 512      // hidden dim
#define KP3 1536    // expanded K' = 3*UU  (slots: ah,al,ah  x  wh,wh,wl)

// step-kernel tiling
#define MT 128      // M per CTA
#define NT 64       // N per CTA
#define KC 64       // K' slots per chunk
#define NCHUNK (KP3 / KC)   // 24

// ---------------- device scratch (no allocations allowed) ----------------
__device__ __nv_bfloat16 g_H[2][BB * KP3];    // hidden state, 3-slot split (12.6 MB)
__device__ float         g_P[VV * UU];        // P = emb @ Wx1 + b1 (20 MB)
__device__ __nv_bfloat16 g_WhT[UU * KP3];     // Wh^T 3-slot split, [n][k'] (1.5 MB)

// ---------------- helpers ----------------
__device__ __forceinline__ uint32_t smem_u32(const void* p) {
    uint32_t a;
    asm("{ .reg .u64 t; cvta.to.shared.u64 t, %1; cvt.u32.u64 %0, t; }" : "=r"(a) : "l"(p));
    return a;
}
__device__ __forceinline__ uint32_t sw128(uint32_t off) { return off ^ ((off >> 3) & 0x70); }

#define CP_ASYNC16(sdst, gsrc) \
    asm volatile("cp.async.cg.shared.global [%0], [%1], 16;" :: "r"(sdst), "l"(gsrc) : "memory")
#define CP_COMMIT() asm volatile("cp.async.commit_group;" ::: "memory")
#define CP_WAIT1()  asm volatile("cp.async.wait_group 1;" ::: "memory")
#define CP_WAIT0()  asm volatile("cp.async.wait_group 0;" ::: "memory")

// split fp32 -> (hi, lo) bf16 bit patterns
__device__ __forceinline__ void split2(float v, uint32_t& hi, uint32_t& lo) {
    __nv_bfloat16 h = __float2bfloat16(v);
    hi = *reinterpret_cast<unsigned short*>(&h);
    float hf = __uint_as_float(hi << 16);
    __nv_bfloat16 l = __float2bfloat16(v - hf);
    lo = *reinterpret_cast<unsigned short*>(&l);
}

// ================= precompute: P = emb @ Wx1 + b1 =================
__global__ __launch_bounds__(256) void p_kernel(
    const float* __restrict__ emb, const float* __restrict__ Wx,
    const float* __restrict__ b1)
{
    __shared__ float As[16][64];
    __shared__ float Bs[16][64];
    const int tid = threadIdx.x;
    const int tx = tid & 15, ty = tid >> 4;
    const int row0 = blockIdx.y * 64, col0 = blockIdx.x * 64;
    const int lm = tid >> 2, lkq = tid & 3;
    const int lk = tid >> 4, lnq = tid & 15;
    float acc[4][4] = {};
    for (int k0 = 0; k0 < 112; k0 += 16) {
        int ea = k0 + lkq * 4;
        int ar = row0 + lm;
        float4 av = (ea < EE && ar < VV) ? *(const float4*)&emb[ar * EE + ea]
                                         : make_float4(0.f, 0.f, 0.f, 0.f);
        int eb = k0 + lk;
        float4 bv = (eb < EE) ? *(const float4*)&Wx[eb * UU + col0 + lnq * 4]
                              : make_float4(0.f, 0.f, 0.f, 0.f);
        __syncthreads();
        As[lkq * 4 + 0][lm] = av.x; As[lkq * 4 + 1][lm] = av.y;
        As[lkq * 4 + 2][lm] = av.z; As[lkq * 4 + 3][lm] = av.w;
        *(float4*)&Bs[lk][lnq * 4] = bv;
        __syncthreads();
        #pragma unroll
        for (int k = 0; k < 16; k++) {
            float4 a = *(const float4*)&As[k][ty * 4];
            float4 b = *(const float4*)&Bs[k][tx * 4];
            float ar4[4] = {a.x, a.y, a.z, a.w};
            float br4[4] = {b.x, b.y, b.z, b.w};
            #pragma unroll
            for (int i = 0; i < 4; i++)
                #pragma unroll
                for (int j = 0; j < 4; j++)
                    acc[i][j] += ar4[i] * br4[j];
        }
    }
    #pragma unroll
    for (int i = 0; i < 4; i++) {
        int r = row0 + ty * 4 + i;
        if (r < VV) {
            #pragma unroll
            for (int j = 0; j < 4; j++) {
                int c = col0 + tx * 4 + j;
                g_P[r * UU + c] = acc[i][j] + b1[c];
            }
        }
    }
}

// ===== precompute: Wh fp32 [k][n] -> WhT' bf16 3-slot split [n][3k..3k+2] = (wh,wh,wl) =====
__global__ __launch_bounds__(256) void wsplit_kernel(const float* __restrict__ Wh)
{
    int idx = blockIdx.x * 256 + threadIdx.x;   // UU*UU = 262144
    int n = idx >> 9;
    int k = idx & 511;
    float w = Wh[k * UU + n];
    uint32_t hi, lo;
    split2(w, hi, lo);
    unsigned short* d = (unsigned short*)g_WhT + (size_t)n * KP3 + 3 * k;
    d[0] = (unsigned short)hi;
    d[1] = (unsigned short)hi;
    d[2] = (unsigned short)lo;
}

// ================= per-timestep step kernel (HMMA mma.sync) =================
// Hout = tanh( Hin @ Wh + P[x[:,t]] ), split-bf16 (3-slot), fp32 accum.
__global__ __launch_bounds__(256) void step_kernel(
    const int* __restrict__ x, int t, int src, int dst, int skip_h)
{
    __shared__ __align__(1024) char sA[2][MT * KC * 2];   // 2 x 16384
    __shared__ __align__(1024) char sB[2][NT * KC * 2];   // 2 x  8192

    const int tid  = threadIdx.x;
    const int wid  = tid >> 5;
    const int lane = tid & 31;
    const int warp_m = wid >> 1;       // 0..3 : 32-row band
    const int warp_n = wid & 1;        // 0..1 : 32-col band
    const int N0 = blockIdx.x * NT;
    const int M0 = blockIdx.y * MT;

    const uint32_t aB = smem_u32(sA);
    const uint32_t bB = smem_u32(sB);

    float acc[2][4][4] = {};

    if (!skip_h) {
        const __nv_bfloat16* __restrict__ Hsrc = g_H[src];

        // ---- cp.async issue for chunk c into buffer d ----
        #define ISSUE(c, d) do {                                                      \
            _Pragma("unroll")                                                         \
            for (int i = 0; i < 4; i++) {                                             \
                int u = tid + i * 256; int m = u >> 3; int kg = u & 7;                \
                uint32_t sd = aB + (d) * 16384 + sw128(m * 128 + kg * 16);            \
                CP_ASYNC16(sd, Hsrc + (size_t)(M0 + m) * KP3 + (c) * KC + kg * 8);    \
            }                                                                         \
            _Pragma("unroll")                                                         \
            for (int i = 0; i < 2; i++) {                                             \
                int u = tid + i * 256; int n = u >> 3; int kg = u & 7;                \
                uint32_t sd = bB + (d) * 8192 + sw128(n * 128 + kg * 16);             \
                CP_ASYNC16(sd, g_WhT + (size_t)(N0 + n) * KP3 + (c) * KC + kg * 8);   \
            }                                                                         \
            CP_COMMIT();                                                              \
        } while (0)

        ISSUE(0, 0);
        for (int c = 0; c < NCHUNK; c++) {
            const int cur = c & 1;
            if (c + 1 < NCHUNK) { ISSUE(c + 1, (c + 1) & 1); CP_WAIT1(); }
            else                { CP_WAIT0(); }
            __syncthreads();

            const uint32_t aT = aB + cur * 16384;
            const uint32_t bT = bB + cur * 8192;
            #pragma unroll
            for (int kf = 0; kf < 4; kf++) {
                uint32_t af[2][4], bf[4][2];
                #pragma unroll
                for (int mi = 0; mi < 2; mi++) {
                    uint32_t addr = aT + sw128(
                        (warp_m * 32 + mi * 16 + (lane & 15)) * 128
                        + (kf * 16 + (lane >> 4) * 8) * 2);
                    asm volatile("ldmatrix.sync.aligned.m8n8.x4.shared.b16 {%0,%1,%2,%3}, [%4];"
                        : "=r"(af[mi][0]), "=r"(af[mi][1]), "=r"(af[mi][2]), "=r"(af[mi][3])
                        : "r"(addr));
                }
                #pragma unroll
                for (int ni = 0; ni < 4; ni++) {
                    uint32_t addr = bT + sw128(
                        (warp_n * 32 + ni * 8 + (lane & 7)) * 128
                        + (kf * 16 + ((lane >> 3) & 1) * 8) * 2);
                    asm volatile("ldmatrix.sync.aligned.m8n8.x2.shared.b16 {%0,%1}, [%2];"
                        : "=r"(bf[ni][0]), "=r"(bf[ni][1]) : "r"(addr));
                }
                #pragma unroll
                for (int mi = 0; mi < 2; mi++)
                    #pragma unroll
                    for (int ni = 0; ni < 4; ni++) {
                        asm volatile(
                            "mma.sync.aligned.m16n8k16.row.col.f32.bf16.bf16.f32 "
                            "{%0,%1,%2,%3}, {%4,%5,%6,%7}, {%8,%9}, {%0,%1,%2,%3};"
                            : "+f"(acc[mi][ni][0]), "+f"(acc[mi][ni][1]),
                              "+f"(acc[mi][ni][2]), "+f"(acc[mi][ni][3])
                            : "r"(af[mi][0]), "r"(af[mi][1]), "r"(af[mi][2]), "r"(af[mi][3]),
                              "r"(bf[ni][0]), "r"(bf[ni][1]));
                    }
            }
            __syncthreads();
        }
        #undef ISSUE
    }

    // ---- epilogue: h = tanh(acc + P[tok]); write 3-slot split H' ----
    {
        const int r = lane >> 2;            // 0..7
        const int q = lane & 3;             // 0..3
        unsigned short* __restrict__ hbase = (unsigned short*)g_H[dst];
        #pragma unroll
        for (int mi = 0; mi < 2; mi++) {
            const int gmA = M0 + warp_m * 32 + mi * 16 + r;
            const int gmB = gmA + 8;
            const int tokA = x[gmA * TT + t];
            const int tokB = x[gmB * TT + t];
            const float* __restrict__ pA = g_P + (size_t)tokA * UU;
            const float* __restrict__ pB = g_P + (size_t)tokB * UU;
            uint32_t* __restrict__ dA = (uint32_t*)(hbase + (size_t)gmA * KP3);
            uint32_t* __restrict__ dB = (uint32_t*)(hbase + (size_t)gmB * KP3);
            #pragma unroll
            for (int ni = 0; ni < 4; ni++) {
                const int gc = N0 + warp_n * 32 + ni * 8 + q * 2;   // even
                float2 pa = *(const float2*)(pA + gc);
                float2 pb = *(const float2*)(pB + gc);
                float h0 = tanhf(acc[mi][ni][0] + pa.x);
                float h1 = tanhf(acc[mi][ni][1] + pa.y);
                float h2 = tanhf(acc[mi][ni][2] + pb.x);
                float h3 = tanhf(acc[mi][ni][3] + pb.y);
                uint32_t h0h, h0l, h1h, h1l, h2h, h2l, h3h, h3l;
                split2(h0, h0h, h0l); split2(h1, h1h, h1l);
                split2(h2, h2h, h2l); split2(h3, h3h, h3l);
                // slots [3c]=ah, [3c+1]=al, [3c+2]=ah for cols gc and gc+1
                const int ub = (3 * gc) >> 1;    // uint32 index (3*gc is even)
                dA[ub + 0] = h0h | (h0l << 16);
                dA[ub + 1] = h0h | (h1h << 16);
                dA[ub + 2] = h1l | (h1h << 16);
                dB[ub + 0] = h2h | (h2l << 16);
                dB[ub + 1] = h2h | (h3h << 16);
                dB[ub + 2] = h3l | (h3h << 16);
            }
        }
    }
}

// ================= output: sigmoid(h @ Wout + bout) =================
__global__ __launch_bounds__(256) void out_kernel(
    const float* __restrict__ Wout, const float* __restrict__ bout,
    float* __restrict__ out, int final_buf)
{
    int gwarp = (blockIdx.x * blockDim.x + threadIdx.x) >> 5;
    int lane  = threadIdx.x & 31;
    if (gwarp >= BB) return;
    const unsigned short* h = (const unsigned short*)g_H[final_buf] + (size_t)gwarp * KP3;
    float s = 0.f;
    for (int k = lane; k < UU; k += 32) {
        float hv = __uint_as_float((uint32_t)h[3 * k] << 16)
                 + __uint_as_float((uint32_t)h[3 * k + 1] << 16);
        s += hv * Wout[k];
    }
    #pragma unroll
    for (int o = 16; o; o >>= 1) s += __shfl_xor_sync(0xFFFFFFFFu, s, o);
    if (lane == 0) out[gwarp] = 1.f / (1.f + expf(-(s + bout[0])));
}

// ================= launcher =================
extern "C" void kernel_launch(void* const* d_in, const int* in_sizes, int n_in,
                              void* d_out, int out_size)
{
    (void)in_sizes; (void)n_in; (void)out_size;
    const int*   x    = (const int*)  d_in[0];
    const float* emb  = (const float*)d_in[1];
    // Wx0/Wh0/b0 (d_in[2..4]) are dead code in the reference.
    const float* Wx1  = (const float*)d_in[5];
    const float* Wh1  = (const float*)d_in[6];
    const float* b1   = (const float*)d_in[7];
    const float* Wout = (const float*)d_in[8];
    const float* bout = (const float*)d_in[9];
    float* out = (float*)d_out;

    p_kernel<<<dim3(8, 157), 256>>>(emb, Wx1, b1);
    wsplit_kernel<<<1024, 256>>>(Wh1);

    dim3 sgrid(UU / NT, BB / MT);   // (8, 16) = 128 CTAs
    for (int t = 0; t < TT; t++) {
        step_kernel<<<sgrid, 256>>>(x, t, t & 1, (t + 1) & 1, (t == 0) ? 1 : 0);
    }
    out_kernel<<<BB / 8, 256>>>(Wout, bout, out, 0);
}

// round 6
// speedup vs baseline: 4.0993x; 1.3810x over previous
#include <cuda_runtime.h>
#include <cuda_bf16.h>
#include <math.h>
#include <stdint.h>

// ---------------- problem constants ----------------
#define BB 2048     // batch
#define TT 80       // time steps
#define EE 100      // embed dim
#define VV 10000    // vocab
#define UU 512      // hidden dim
#define KP2 1024    // stored K' = 2*UU : [0:512]=hi, [512:1024]=lo

#define NCTA 128    // persistent grid (<= #SMs, 1 CTA/SM)
#define MT 128
#define NT 64

// smem: B resident 16 blocks x 8KB = 128KB, then 3 A stages x 32KB
#define SM_B    0
#define SM_A    131072
#define SM_TOT  (131072 + 3 * 32768)   // 229376 bytes

// ---------------- device scratch ----------------
__device__ __align__(16) __nv_bfloat16 g_H[2][BB * KP2];   // 8 MB
__device__ __align__(16) float         g_P[VV * UU];       // 20 MB
__device__ __align__(16) __nv_bfloat16 g_WhT[UU * KP2];    // 1 MB
__device__ __align__(16) int           g_xT[TT * BB];
__device__ unsigned int g_bar;

// ---------------- helpers ----------------
__device__ __forceinline__ uint32_t smem_u32(const void* p) {
    uint32_t a;
    asm("{ .reg .u64 t; cvta.to.shared.u64 t, %1; cvt.u32.u64 %0, t; }" : "=r"(a) : "l"(p));
    return a;
}
__device__ __forceinline__ uint32_t sw128(uint32_t off) { return off ^ ((off >> 3) & 0x70); }

#define CP_ASYNC16(sdst, gsrc) \
    asm volatile("cp.async.cg.shared.global [%0], [%1], 16;" :: "r"(sdst), "l"(gsrc) : "memory")
#define CP_COMMIT() asm volatile("cp.async.commit_group;" ::: "memory")
#define CP_WAITN(n) asm volatile("cp.async.wait_group %0;" :: "n"(n) : "memory")

__device__ __forceinline__ void split2(float v, uint32_t& hi, uint32_t& lo) {
    __nv_bfloat16 h = __float2bfloat16(v);
    hi = *reinterpret_cast<unsigned short*>(&h);
    float hf = __uint_as_float(hi << 16);
    __nv_bfloat16 l = __float2bfloat16(v - hf);
    lo = *reinterpret_cast<unsigned short*>(&l);
}

// cooperative-groups-style grid barrier (1 wave guaranteed: 128 CTAs, 1/SM)
__device__ __forceinline__ void gbar(unsigned int target) {
    __syncthreads();
    if (threadIdx.x == 0) {
        asm volatile("red.release.gpu.global.add.u32 [%0], 1;" :: "l"(&g_bar) : "memory");
        unsigned int v;
        do {
            asm volatile("ld.acquire.gpu.global.u32 %0, [%1];" : "=r"(v) : "l"(&g_bar) : "memory");
        } while ((int)(v - target) < 0);
    }
    __syncthreads();
}

// ================= tiny setup kernels =================
__global__ void reset_kernel() { g_bar = 0; }

__global__ __launch_bounds__(256) void xt_kernel(const int* __restrict__ x) {
    int idx = blockIdx.x * 256 + threadIdx.x;          // idx = t*BB + b
    if (idx < TT * BB) {
        int t = idx / BB, b = idx - t * BB;
        g_xT[idx] = x[b * TT + t];
    }
}

// Wh fp32 [k][n] -> WhT' bf16 2-slot: g_WhT[n][k]=hi, g_WhT[n][512+k]=lo
__global__ __launch_bounds__(256) void wsplit_kernel(const float* __restrict__ Wh) {
    int idx = blockIdx.x * 256 + threadIdx.x;          // UU*UU
    int n = idx >> 9, k = idx & 511;
    uint32_t hi, lo;
    split2(Wh[k * UU + n], hi, lo);
    unsigned short* d = (unsigned short*)g_WhT + (size_t)n * KP2;
    d[k]       = (unsigned short)hi;
    d[512 + k] = (unsigned short)lo;
}

// P = emb @ Wx1 + b1
__global__ __launch_bounds__(256) void p_kernel(
    const float* __restrict__ emb, const float* __restrict__ Wx,
    const float* __restrict__ b1)
{
    __shared__ float As[16][64];
    __shared__ float Bs[16][64];
    const int tid = threadIdx.x;
    const int tx = tid & 15, ty = tid >> 4;
    const int row0 = blockIdx.y * 64, col0 = blockIdx.x * 64;
    const int lm = tid >> 2, lkq = tid & 3;
    const int lk = tid >> 4, lnq = tid & 15;
    float acc[4][4] = {};
    for (int k0 = 0; k0 < 112; k0 += 16) {
        int ea = k0 + lkq * 4;
        int ar = row0 + lm;
        float4 av = (ea < EE && ar < VV) ? *(const float4*)&emb[ar * EE + ea]
                                         : make_float4(0.f, 0.f, 0.f, 0.f);
        int eb = k0 + lk;
        float4 bv = (eb < EE) ? *(const float4*)&Wx[eb * UU + col0 + lnq * 4]
                              : make_float4(0.f, 0.f, 0.f, 0.f);
        __syncthreads();
        As[lkq * 4 + 0][lm] = av.x; As[lkq * 4 + 1][lm] = av.y;
        As[lkq * 4 + 2][lm] = av.z; As[lkq * 4 + 3][lm] = av.w;
        *(float4*)&Bs[lk][lnq * 4] = bv;
        __syncthreads();
        #pragma unroll
        for (int k = 0; k < 16; k++) {
            float4 a = *(const float4*)&As[k][ty * 4];
            float4 b = *(const float4*)&Bs[k][tx * 4];
            float ar4[4] = {a.x, a.y, a.z, a.w};
            float br4[4] = {b.x, b.y, b.z, b.w};
            #pragma unroll
            for (int i = 0; i < 4; i++)
                #pragma unroll
                for (int j = 0; j < 4; j++)
                    acc[i][j] += ar4[i] * br4[j];
        }
    }
    #pragma unroll
    for (int i = 0; i < 4; i++) {
        int r = row0 + ty * 4 + i;
        if (r < VV)
            #pragma unroll
            for (int j = 0; j < 4; j++)
                g_P[r * UU + col0 + tx * 4 + j] = acc[i][j] + b1[col0 + tx * 4 + j];
    }
}

// ================= persistent RNN kernel =================
__device__ __forceinline__ void compute_stage(
    uint32_t aT, uint32_t bB, int kb, int warp_m, int warp_n, int lane,
    float acc[2][4][4])
{
    #pragma unroll
    for (int kf = 0; kf < 4; kf++) {
        uint32_t a_h[2][4], a_l[2][4];
        #pragma unroll
        for (int mi = 0; mi < 2; mi++) {
            uint32_t off = sw128((warp_m * 32 + mi * 16 + (lane & 15)) * 128
                                 + (kf * 16 + (lane >> 4) * 8) * 2);
            asm volatile("ldmatrix.sync.aligned.m8n8.x4.shared.b16 {%0,%1,%2,%3}, [%4];"
                : "=r"(a_h[mi][0]), "=r"(a_h[mi][1]), "=r"(a_h[mi][2]), "=r"(a_h[mi][3])
                : "r"(aT + off));
            asm volatile("ldmatrix.sync.aligned.m8n8.x4.shared.b16 {%0,%1,%2,%3}, [%4];"
                : "=r"(a_l[mi][0]), "=r"(a_l[mi][1]), "=r"(a_l[mi][2]), "=r"(a_l[mi][3])
                : "r"(aT + 16384 + off));
        }
        uint32_t b_h[4][2], b_l[4][2];
        #pragma unroll
        for (int ni = 0; ni < 4; ni++) {
            uint32_t off = sw128((warp_n * 32 + ni * 8 + (lane & 7)) * 128
                                 + (kf * 16 + ((lane >> 3) & 1) * 8) * 2);
            asm volatile("ldmatrix.sync.aligned.m8n8.x2.shared.b16 {%0,%1}, [%2];"
                : "=r"(b_h[ni][0]), "=r"(b_h[ni][1]) : "r"(bB + kb * 8192 + off));
            asm volatile("ldmatrix.sync.aligned.m8n8.x2.shared.b16 {%0,%1}, [%2];"
                : "=r"(b_l[ni][0]), "=r"(b_l[ni][1]) : "r"(bB + (kb + 8) * 8192 + off));
        }
        #pragma unroll
        for (int mi = 0; mi < 2; mi++)
            #pragma unroll
            for (int ni = 0; ni < 4; ni++) {
                #define MMA(AH, BH)                                                   \
                    asm volatile(                                                     \
                        "mma.sync.aligned.m16n8k16.row.col.f32.bf16.bf16.f32 "        \
                        "{%0,%1,%2,%3}, {%4,%5,%6,%7}, {%8,%9}, {%0,%1,%2,%3};"       \
                        : "+f"(acc[mi][ni][0]), "+f"(acc[mi][ni][1]),                 \
                          "+f"(acc[mi][ni][2]), "+f"(acc[mi][ni][3])                  \
                        : "r"(AH[mi][0]), "r"(AH[mi][1]), "r"(AH[mi][2]),             \
                          "r"(AH[mi][3]), "r"(BH[ni][0]), "r"(BH[ni][1]))
                MMA(a_h, b_h);   // ah * wh
                MMA(a_l, b_h);   // al * wh
                MMA(a_h, b_l);   // ah * wl
                #undef MMA
            }
    }
}

__global__ __launch_bounds__(256, 1) void rnn_kernel(
    const float* __restrict__ Wout, const float* __restrict__ bout,
    float* __restrict__ out)
{
    extern __shared__ char smem[];
    const uint32_t bB = smem_u32(smem) + SM_B;
    const uint32_t aB = smem_u32(smem) + SM_A;

    const int tid  = threadIdx.x;
    const int wid  = tid >> 5;
    const int lane = tid & 31;
    const int warp_m = wid >> 1;
    const int warp_n = wid & 1;
    const int n_tile = blockIdx.x & 7;
    const int m_tile = blockIdx.x >> 3;
    const int N0 = n_tile * NT;
    const int M0 = m_tile * MT;

    // ---- load resident B slice (64 n x 1024 k') once ----
    #pragma unroll 8
    for (int i = 0; i < 32; i++) {
        int u = tid + i * 256;           // 8192 16B units
        int kb = u >> 9, rm = u & 511;
        int n = rm >> 3, kg = rm & 7;
        CP_ASYNC16(bB + kb * 8192 + sw128(n * 128 + kg * 16),
                   g_WhT + (size_t)(N0 + n) * KP2 + kb * 64 + kg * 8);
    }
    CP_COMMIT(); CP_WAITN(0);
    __syncthreads();

    unsigned int bar_target = NCTA;

    #define ISSUE_A(kb, st) do {                                                      \
        _Pragma("unroll")                                                             \
        for (int i = 0; i < 4; i++) {                                                 \
            int u = tid + i * 256; int m = u >> 3; int kg = u & 7;                    \
            uint32_t sd = aB + (st) * 32768 + sw128(m * 128 + kg * 16);               \
            const __nv_bfloat16* gs = Hsrc + (size_t)(M0 + m) * KP2 + (kb) * 64 + kg * 8; \
            CP_ASYNC16(sd, gs);                                                       \
            CP_ASYNC16(sd + 16384, gs + 512);                                         \
        }                                                                             \
        CP_COMMIT();                                                                  \
    } while (0)

    for (int t = 0; t < TT; t++) {
        const int src = t & 1, dst = src ^ 1;
        float acc[2][4][4] = {};

        if (t > 0) {
            const __nv_bfloat16* __restrict__ Hsrc = g_H[src];
            ISSUE_A(0, 0); ISSUE_A(1, 1); ISSUE_A(2, 2);
            #pragma unroll
            for (int kb = 0; kb < 8; kb++) {
                if (kb < 6)       CP_WAITN(2);
                else if (kb == 6) CP_WAITN(1);
                else              CP_WAITN(0);
                __syncthreads();
                compute_stage(aB + (kb % 3) * 32768, bB, kb, warp_m, warp_n, lane, acc);
                __syncthreads();
                if (kb <= 4) ISSUE_A(kb + 3, kb % 3);
            }
        }

        // ---- epilogue: h = tanh(acc + P[tok]); write 2-slot split ----
        {
            const int r = lane >> 2, q = lane & 3;
            unsigned short* __restrict__ hbase = (unsigned short*)g_H[dst];
            const int* __restrict__ xrow = g_xT + t * BB;
            #pragma unroll
            for (int mi = 0; mi < 2; mi++) {
                const int gmA = M0 + warp_m * 32 + mi * 16 + r;
                const int gmB = gmA + 8;
                const float* __restrict__ pA = g_P + (size_t)xrow[gmA] * UU;
                const float* __restrict__ pB = g_P + (size_t)xrow[gmB] * UU;
                uint32_t* __restrict__ dA = (uint32_t*)(hbase + (size_t)gmA * KP2);
                uint32_t* __restrict__ dB = (uint32_t*)(hbase + (size_t)gmB * KP2);
                #pragma unroll
                for (int ni = 0; ni < 4; ni++) {
                    const int gc = N0 + warp_n * 32 + ni * 8 + q * 2;
                    float2 pa = *(const float2*)(pA + gc);
                    float2 pb = *(const float2*)(pB + gc);
                    float h0 = tanhf(acc[mi][ni][0] + pa.x);
                    float h1 = tanhf(acc[mi][ni][1] + pa.y);
                    float h2 = tanhf(acc[mi][ni][2] + pb.x);
                    float h3 = tanhf(acc[mi][ni][3] + pb.y);
                    uint32_t h0h, h0l, h1h, h1l, h2h, h2l, h3h, h3l;
                    split2(h0, h0h, h0l); split2(h1, h1h, h1l);
                    split2(h2, h2h, h2l); split2(h3, h3h, h3l);
                    const int ui = gc >> 1;
                    dA[ui]       = h0h | (h1h << 16);
                    dA[256 + ui] = h0l | (h1l << 16);
                    dB[ui]       = h2h | (h3h << 16);
                    dB[256 + ui] = h2l | (h3l << 16);
                }
            }
        }

        gbar(bar_target);
        bar_target += NCTA;
    }
    #undef ISSUE_A

    // ---- output phase: rows M0..M0+127, done by the 16 CTAs with n_tile==0 ----
    if (n_tile == 0) {
        const unsigned short* __restrict__ hb = (const unsigned short*)g_H[0];
        const float bo = bout[0];
        #pragma unroll 4
        for (int r = 0; r < 16; r++) {
            const int gm = M0 + wid * 16 + r;
            const unsigned short* row = hb + (size_t)gm * KP2;
            float s = 0.f;
            #pragma unroll
            for (int k = lane; k < UU; k += 32) {
                float hv = __uint_as_float((uint32_t)row[k] << 16)
                         + __uint_as_float((uint32_t)row[512 + k] << 16);
                s += hv * Wout[k];
            }
            #pragma unroll
            for (int o = 16; o; o >>= 1) s += __shfl_xor_sync(0xFFFFFFFFu, s, o);
            if (lane == 0) out[gm] = 1.f / (1.f + expf(-(s + bo)));
        }
    }
}

// ================= launcher =================
extern "C" void kernel_launch(void* const* d_in, const int* in_sizes, int n_in,
                              void* d_out, int out_size)
{
    (void)in_sizes; (void)n_in; (void)out_size;
    const int*   x    = (const int*)  d_in[0];
    const float* emb  = (const float*)d_in[1];
    // Wx0/Wh0/b0 (d_in[2..4]) are dead code in the reference.
    const float* Wx1  = (const float*)d_in[5];
    const float* Wh1  = (const float*)d_in[6];
    const float* b1   = (const float*)d_in[7];
    const float* Wout = (const float*)d_in[8];
    const float* bout = (const float*)d_in[9];
    float* out = (float*)d_out;

    cudaFuncSetAttribute(rnn_kernel, cudaFuncAttributeMaxDynamicSharedMemorySize, SM_TOT);

    reset_kernel<<<1, 1>>>();
    xt_kernel<<<(TT * BB + 255) / 256, 256>>>(x);
    wsplit_kernel<<<UU * UU / 256, 256>>>(Wh1);
    p_kernel<<<dim3(8, 157), 256>>>(emb, Wx1, b1);
    rnn_kernel<<<NCTA, 256, SM_TOT>>>(Wout, bout, out);
}

// round 8
// speedup vs baseline: 4.1035x; 1.0010x over previous
#include <cuda_runtime.h>
#include <cuda_bf16.h>
#include <math.h>
#include <stdint.h>

// ---------------- problem constants ----------------
#define BB 2048     // batch
#define TT 80       // time steps
#define EE 100      // embed dim
#define VV 10000    // vocab
#define UU 512      // hidden dim
#define KP2 1024    // stored K' = 2*UU : [0:512]=hi, [512:1024]=lo

#define NCTA 128    // persistent grid (1 CTA/SM, single wave)
#define MT 128
#define NT 64

// smem: B resident 16 blocks x 8KB = 128KB, then 3 A stages x 32KB
#define SM_B    0
#define SM_A    131072
#define SM_TOT  (131072 + 3 * 32768)   // 229376 bytes

// ---------------- device scratch ----------------
__device__ __align__(16) __nv_bfloat16 g_H[2][BB * KP2];   // 8 MB
__device__ __align__(16) float         g_P[VV * UU];       // 20 MB
__device__ __align__(16) __nv_bfloat16 g_WhT[UU * KP2];    // 1 MB
__device__ __align__(16) int           g_xT[TT * BB];
__device__ unsigned int g_bars[16 * 32];   // one counter per m-group, 128B apart

// ---------------- helpers ----------------
__device__ __forceinline__ uint32_t smem_u32(const void* p) {
    uint32_t a;
    asm("{ .reg .u64 t; cvta.to.shared.u64 t, %1; cvt.u32.u64 %0, t; }" : "=r"(a) : "l"(p));
    return a;
}
__device__ __forceinline__ uint32_t sw128(uint32_t off) { return off ^ ((off >> 3) & 0x70); }

#define CP_ASYNC16(sdst, gsrc) \
    asm volatile("cp.async.cg.shared.global [%0], [%1], 16;" :: "r"(sdst), "l"(gsrc) : "memory")
#define CP_COMMIT() asm volatile("cp.async.commit_group;" ::: "memory")
#define CP_WAITN(n) asm volatile("cp.async.wait_group %0;" :: "n"(n) : "memory")

__device__ __forceinline__ void split2(float v, uint32_t& hi, uint32_t& lo) {
    __nv_bfloat16 h = __float2bfloat16(v);
    hi = *reinterpret_cast<unsigned short*>(&h);
    float hf = __uint_as_float(hi << 16);
    __nv_bfloat16 l = __float2bfloat16(v - hf);
    lo = *reinterpret_cast<unsigned short*>(&l);
}

// fast tanh: 1 - 2/(e^{2x}+1); inf-safe for all reachable inputs, ~ulp-level error
__device__ __forceinline__ float fast_tanh(float x) {
    float e = __expf(2.f * x);
    return 1.f - __fdividef(2.f, e + 1.f);
}

// per-m-group barrier: 8 CTAs arrive on a dedicated counter
__device__ __forceinline__ void gbar_group(unsigned int* ctr, unsigned int target) {
    __syncthreads();
    if (threadIdx.x == 0) {
        asm volatile("red.release.gpu.global.add.u32 [%0], 1;" :: "l"(ctr) : "memory");
        unsigned int v;
        do {
            asm volatile("ld.acquire.gpu.global.u32 %0, [%1];" : "=r"(v) : "l"(ctr) : "memory");
        } while ((int)(v - target) < 0);
    }
    __syncthreads();
}

// ================= tiny setup kernels =================
__global__ void reset_kernel() {
    if (threadIdx.x < 16) g_bars[threadIdx.x * 32] = 0;
}

__global__ __launch_bounds__(256) void xt_kernel(const int* __restrict__ x) {
    int idx = blockIdx.x * 256 + threadIdx.x;          // idx = t*BB + b
    if (idx < TT * BB) {
        int t = idx / BB, b = idx - t * BB;
        g_xT[idx] = x[b * TT + t];
    }
}

// Wh fp32 [k][n] -> WhT' bf16 2-slot: g_WhT[n][k]=hi, g_WhT[n][512+k]=lo
__global__ __launch_bounds__(256) void wsplit_kernel(const float* __restrict__ Wh) {
    int idx = blockIdx.x * 256 + threadIdx.x;          // UU*UU
    int n = idx >> 9, k = idx & 511;
    uint32_t hi, lo;
    split2(Wh[k * UU + n], hi, lo);
    unsigned short* d = (unsigned short*)g_WhT + (size_t)n * KP2;
    d[k]       = (unsigned short)hi;
    d[512 + k] = (unsigned short)lo;
}

// P = emb @ Wx1 + b1
__global__ __launch_bounds__(256) void p_kernel(
    const float* __restrict__ emb, const float* __restrict__ Wx,
    const float* __restrict__ b1)
{
    __shared__ float As[16][64];
    __shared__ float Bs[16][64];
    const int tid = threadIdx.x;
    const int tx = tid & 15, ty = tid >> 4;
    const int row0 = blockIdx.y * 64, col0 = blockIdx.x * 64;
    const int lm = tid >> 2, lkq = tid & 3;
    const int lk = tid >> 4, lnq = tid & 15;
    float acc[4][4] = {};
    for (int k0 = 0; k0 < 112; k0 += 16) {
        int ea = k0 + lkq * 4;
        int ar = row0 + lm;
        float4 av = (ea < EE && ar < VV) ? *(const float4*)&emb[ar * EE + ea]
                                         : make_float4(0.f, 0.f, 0.f, 0.f);
        int eb = k0 + lk;
        float4 bv = (eb < EE) ? *(const float4*)&Wx[eb * UU + col0 + lnq * 4]
                              : make_float4(0.f, 0.f, 0.f, 0.f);
        __syncthreads();
        As[lkq * 4 + 0][lm] = av.x; As[lkq * 4 + 1][lm] = av.y;
        As[lkq * 4 + 2][lm] = av.z; As[lkq * 4 + 3][lm] = av.w;
        *(float4*)&Bs[lk][lnq * 4] = bv;
        __syncthreads();
        #pragma unroll
        for (int k = 0; k < 16; k++) {
            float4 a = *(const float4*)&As[k][ty * 4];
            float4 b = *(const float4*)&Bs[k][tx * 4];
            float ar4[4] = {a.x, a.y, a.z, a.w};
            float br4[4] = {b.x, b.y, b.z, b.w};
            #pragma unroll
            for (int i = 0; i < 4; i++)
                #pragma unroll
                for (int j = 0; j < 4; j++)
                    acc[i][j] += ar4[i] * br4[j];
        }
    }
    #pragma unroll
    for (int i = 0; i < 4; i++) {
        int r = row0 + ty * 4 + i;
        if (r < VV)
            #pragma unroll
            for (int j = 0; j < 4; j++)
                g_P[r * UU + col0 + tx * 4 + j] = acc[i][j] + b1[col0 + tx * 4 + j];
    }
}

// ================= persistent RNN kernel =================
__device__ __forceinline__ void compute_stage(
    uint32_t aT, uint32_t bB, int kb, int warp_m, int warp_n, int lane,
    float acc[2][4][4])
{
    #pragma unroll
    for (int kf = 0; kf < 4; kf++) {
        uint32_t a_h[2][4], a_l[2][4];
        #pragma unroll
        for (int mi = 0; mi < 2; mi++) {
            uint32_t off = sw128((warp_m * 32 + mi * 16 + (lane & 15)) * 128
                                 + (kf * 16 + (lane >> 4) * 8) * 2);
            asm volatile("ldmatrix.sync.aligned.m8n8.x4.shared.b16 {%0,%1,%2,%3}, [%4];"
                : "=r"(a_h[mi][0]), "=r"(a_h[mi][1]), "=r"(a_h[mi][2]), "=r"(a_h[mi][3])
                : "r"(aT + off));
            asm volatile("ldmatrix.sync.aligned.m8n8.x4.shared.b16 {%0,%1,%2,%3}, [%4];"
                : "=r"(a_l[mi][0]), "=r"(a_l[mi][1]), "=r"(a_l[mi][2]), "=r"(a_l[mi][3])
                : "r"(aT + 16384 + off));
        }
        // B fragments: x4 loads deliver two n8k16 tiles (ni pair) at once
        uint32_t b_h[4][2], b_l[4][2];
        #pragma unroll
        for (int ni2 = 0; ni2 < 2; ni2++) {
            const int g = lane >> 3;
            uint32_t off = sw128((warp_n * 32 + ni2 * 16 + (g >> 1) * 8 + (lane & 7)) * 128
                                 + (kf * 16 + (g & 1) * 8) * 2);
            asm volatile("ldmatrix.sync.aligned.m8n8.x4.shared.b16 {%0,%1,%2,%3}, [%4];"
                : "=r"(b_h[ni2 * 2][0]), "=r"(b_h[ni2 * 2][1]),
                  "=r"(b_h[ni2 * 2 + 1][0]), "=r"(b_h[ni2 * 2 + 1][1])
                : "r"(bB + kb * 8192 + off));
            asm volatile("ldmatrix.sync.aligned.m8n8.x4.shared.b16 {%0,%1,%2,%3}, [%4];"
                : "=r"(b_l[ni2 * 2][0]), "=r"(b_l[ni2 * 2][1]),
                  "=r"(b_l[ni2 * 2 + 1][0]), "=r"(b_l[ni2 * 2 + 1][1])
                : "r"(bB + (kb + 8) * 8192 + off));
        }
        #pragma unroll
        for (int mi = 0; mi < 2; mi++)
            #pragma unroll
            for (int ni = 0; ni < 4; ni++) {
                #define MMA(AH, BH)                                                   \
                    asm volatile(                                                     \
                        "mma.sync.aligned.m16n8k16.row.col.f32.bf16.bf16.f32 "        \
                        "{%0,%1,%2,%3}, {%4,%5,%6,%7}, {%8,%9}, {%0,%1,%2,%3};"       \
                        : "+f"(acc[mi][ni][0]), "+f"(acc[mi][ni][1]),                 \
                          "+f"(acc[mi][ni][2]), "+f"(acc[mi][ni][3])                  \
                        : "r"(AH[mi][0]), "r"(AH[mi][1]), "r"(AH[mi][2]),             \
                          "r"(AH[mi][3]), "r"(BH[ni][0]), "r"(BH[ni][1]))
                MMA(a_h, b_h);   // ah * wh
                MMA(a_l, b_h);   // al * wh
                MMA(a_h, b_l);   // ah * wl
                #undef MMA
            }
    }
}

__global__ __launch_bounds__(256, 1) void rnn_kernel(
    const float* __restrict__ Wout, const float* __restrict__ bout,
    float* __restrict__ out)
{
    extern __shared__ char smem[];
    const uint32_t bB = smem_u32(smem) + SM_B;
    const uint32_t aB = smem_u32(smem) + SM_A;

    const int tid  = threadIdx.x;
    const int wid  = tid >> 5;
    const int lane = tid & 31;
    const int warp_m = wid >> 1;
    const int warp_n = wid & 1;
    const int n_tile = blockIdx.x & 7;
    const int m_tile = blockIdx.x >> 3;
    const int N0 = n_tile * NT;
    const int M0 = m_tile * MT;
    unsigned int* const my_bar = &g_bars[m_tile * 32];

    // ---- load resident B slice (64 n x 1024 k') once ----
    #pragma unroll 8
    for (int i = 0; i < 32; i++) {
        int u = tid + i * 256;           // 8192 16B units
        int kb = u >> 9, rm = u & 511;
        int n = rm >> 3, kg = rm & 7;
        CP_ASYNC16(bB + kb * 8192 + sw128(n * 128 + kg * 16),
                   g_WhT + (size_t)(N0 + n) * KP2 + kb * 64 + kg * 8);
    }
    CP_COMMIT(); CP_WAITN(0);
    __syncthreads();

    unsigned int bar_target = 8;

    #define ISSUE_A(kb, st) do {                                                      \
        _Pragma("unroll")                                                             \
        for (int i = 0; i < 4; i++) {                                                 \
            int u = tid + i * 256; int m = u >> 3; int kg = u & 7;                    \
            uint32_t sd = aB + (st) * 32768 + sw128(m * 128 + kg * 16);               \
            const __nv_bfloat16* gs = Hsrc + (size_t)(M0 + m) * KP2 + (kb) * 64 + kg * 8; \
            CP_ASYNC16(sd, gs);                                                       \
            CP_ASYNC16(sd + 16384, gs + 512);                                         \
        }                                                                             \
        CP_COMMIT();                                                                  \
    } while (0)

    const int r = lane >> 2, q = lane & 3;
    const int gmA_base = M0 + warp_m * 32 + r;

    for (int t = 0; t < TT; t++) {
        const int src = t & 1, dst = src ^ 1;
        float acc[2][4][4] = {};

        // hoist token loads (latency hidden under MMA loop)
        const int* __restrict__ xrow = g_xT + t * BB;
        const int tokA0 = xrow[gmA_base];
        const int tokB0 = xrow[gmA_base + 8];
        const int tokA1 = xrow[gmA_base + 16];
        const int tokB1 = xrow[gmA_base + 24];

        if (t > 0) {
            const __nv_bfloat16* __restrict__ Hsrc = g_H[src];
            ISSUE_A(0, 0); ISSUE_A(1, 1);     // 2-deep prefetch
            #pragma unroll
            for (int kb = 0; kb < 8; kb++) {
                // wait for MY copies of chunk kb, THEN sync to publish everyone's
                if (kb < 7) CP_WAITN(1); else CP_WAITN(0);
                __syncthreads();
                // refill stage (kb+2)%3 (last read at compute kb-1, done pre-sync)
                if (kb <= 5) ISSUE_A(kb + 2, (kb + 2) % 3);
                compute_stage(aB + (kb % 3) * 32768, bB, kb, warp_m, warp_n, lane, acc);
            }
        }

        // ---- epilogue: h = tanh(acc + P[tok]); write 2-slot split ----
        {
            unsigned short* __restrict__ hbase = (unsigned short*)g_H[dst];
            const int toks[2][2] = {{tokA0, tokB0}, {tokA1, tokB1}};
            #pragma unroll
            for (int mi = 0; mi < 2; mi++) {
                const int gmA = gmA_base + mi * 16;
                const int gmB = gmA + 8;
                const float* __restrict__ pA = g_P + (size_t)toks[mi][0] * UU;
                const float* __restrict__ pB = g_P + (size_t)toks[mi][1] * UU;
                uint32_t* __restrict__ dA = (uint32_t*)(hbase + (size_t)gmA * KP2);
                uint32_t* __restrict__ dB = (uint32_t*)(hbase + (size_t)gmB * KP2);
                #pragma unroll
                for (int ni = 0; ni < 4; ni++) {
                    const int gc = N0 + warp_n * 32 + ni * 8 + q * 2;
                    float2 pa = *(const float2*)(pA + gc);
                    float2 pb = *(const float2*)(pB + gc);
                    float h0 = fast_tanh(acc[mi][ni][0] + pa.x);
                    float h1 = fast_tanh(acc[mi][ni][1] + pa.y);
                    float h2 = fast_tanh(acc[mi][ni][2] + pb.x);
                    float h3 = fast_tanh(acc[mi][ni][3] + pb.y);
                    uint32_t h0h, h0l, h1h, h1l, h2h, h2l, h3h, h3l;
                    split2(h0, h0h, h0l); split2(h1, h1h, h1l);
                    split2(h2, h2h, h2l); split2(h3, h3h, h3l);
                    const int ui = gc >> 1;
                    dA[ui]       = h0h | (h1h << 16);
                    dA[256 + ui] = h0l | (h1l << 16);
                    dB[ui]       = h2h | (h3h << 16);
                    dB[256 + ui] = h2l | (h3l << 16);
                }
            }
        }

        gbar_group(my_bar, bar_target);
        bar_target += 8;
    }
    #undef ISSUE_A

    // ---- output phase: rows M0..M0+127, done by the 16 CTAs with n_tile==0 ----
    if (n_tile == 0) {
        const unsigned short* __restrict__ hb = (const unsigned short*)g_H[0];
        const float bo = bout[0];
        #pragma unroll 4
        for (int rr = 0; rr < 16; rr++) {
            const int gm = M0 + wid * 16 + rr;
            const unsigned short* row = hb + (size_t)gm * KP2;
            float s = 0.f;
            #pragma unroll
            for (int k = lane; k < UU; k += 32) {
                float hv = __uint_as_float((uint32_t)row[k] << 16)
                         + __uint_as_float((uint32_t)row[512 + k] << 16);
                s += hv * Wout[k];
            }
            #pragma unroll
            for (int o = 16; o; o >>= 1) s += __shfl_xor_sync(0xFFFFFFFFu, s, o);
            if (lane == 0) out[gm] = 1.f / (1.f + expf(-(s + bo)));
        }
    }
}

// ================= launcher =================
extern "C" void kernel_launch(void* const* d_in, const int* in_sizes, int n_in,
                              void* d_out, int out_size)
{
    (void)in_sizes; (void)n_in; (void)out_size;
    const int*   x    = (const int*)  d_in[0];
    const float* emb  = (const float*)d_in[1];
    // Wx0/Wh0/b0 (d_in[2..4]) are dead code in the reference.
    const float* Wx1  = (const float*)d_in[5];
    const float* Wh1  = (const float*)d_in[6];
    const float* b1   = (const float*)d_in[7];
    const float* Wout = (const float*)d_in[8];
    const float* bout = (const float*)d_in[9];
    float* out = (float*)d_out;

    cudaFuncSetAttribute(rnn_kernel, cudaFuncAttributeMaxDynamicSharedMemorySize, SM_TOT);

    reset_kernel<<<1, 32>>>();
    xt_kernel<<<(TT * BB + 255) / 256, 256>>>(x);
    wsplit_kernel<<<UU * UU / 256, 256>>>(Wh1);
    p_kernel<<<dim3(8, 157), 256>>>(emb, Wx1, b1);
    rnn_kernel<<<NCTA, 256, SM_TOT>>>(Wout, bout, out);
}

// round 9
// speedup vs baseline: 5.4326x; 1.3239x over previous
#include <cuda_runtime.h>
#include <cuda_bf16.h>
#include <math.h>
#include <stdint.h>

// ---------------- problem constants ----------------
#define BB 2048     // batch
#define TT 80       // time steps
#define EE 100      // embed dim
#define VV 10000    // vocab
#define UU 512      // hidden dim

#define NCTA 128    // persistent grid (1 CTA/SM, single wave)
#define MT 128
#define NT 64

// H row layout: 1024 bytes = [0:512) level-0 int8, [512:1024) level-1 int8
#define HROW 1024

// smem: B resident 8 blocks x 8KB = 64KB, then 4 A stages x 32KB = 128KB
#define SM_B    0
#define SM_A    65536
#define SM_TOT  (65536 + 4 * 32768)    // 196608 bytes

// quant constants: h = i1/127 + i2/16256 ; w = j1*s1 + j2*s1/128
#define C_A1 (1.f / 127.f)
#define C_A2 (1.f / 16256.f)

// ---------------- device scratch ----------------
__device__ __align__(16) uint8_t g_Hq[2][BB * HROW];   // 4 MB
__device__ __align__(16) float   g_P[VV * UU];         // 20 MB
__device__ __align__(16) int8_t  g_Wq[UU * HROW];      // 512 KB ([n][1024]: L0|L1)
__device__ __align__(16) int     g_xT[TT * BB];
__device__ unsigned int g_bars[16 * 32];
__device__ unsigned int g_wmax;

// ---------------- helpers ----------------
__device__ __forceinline__ uint32_t smem_u32(const void* p) {
    uint32_t a;
    asm("{ .reg .u64 t; cvta.to.shared.u64 t, %1; cvt.u32.u64 %0, t; }" : "=r"(a) : "l"(p));
    return a;
}
__device__ __forceinline__ uint32_t sw128(uint32_t off) { return off ^ ((off >> 3) & 0x70); }

#define CP_ASYNC16(sdst, gsrc) \
    asm volatile("cp.async.cg.shared.global [%0], [%1], 16;" :: "r"(sdst), "l"(gsrc) : "memory")
#define CP_COMMIT() asm volatile("cp.async.commit_group;" ::: "memory")
#define CP_WAITN(n) asm volatile("cp.async.wait_group %0;" :: "n"(n) : "memory")

// fast tanh: 1 - 2/(e^{2x}+1); inf-safe, ~ulp-level error
__device__ __forceinline__ float fast_tanh(float x) {
    float e = __expf(2.f * x);
    return 1.f - __fdividef(2.f, e + 1.f);
}

// per-m-group barrier: 8 CTAs arrive on a dedicated counter
__device__ __forceinline__ void gbar_group(unsigned int* ctr, unsigned int target) {
    __syncthreads();
    if (threadIdx.x == 0) {
        asm volatile("red.release.gpu.global.add.u32 [%0], 1;" :: "l"(ctr) : "memory");
        unsigned int v;
        do {
            asm volatile("ld.acquire.gpu.global.u32 %0, [%1];" : "=r"(v) : "l"(ctr) : "memory");
        } while ((int)(v - target) < 0);
    }
    __syncthreads();
}

// quantize h in (-1,1) to two int8 levels
__device__ __forceinline__ void hquant(float h, int& i1, int& i2) {
    i1 = __float2int_rn(h * 127.f);
    float r = h - (float)i1 * C_A1;
    i2 = __float2int_rn(r * 16256.f);
}

// ================= tiny setup kernels =================
__global__ void reset_kernel() {
    if (threadIdx.x < 16) g_bars[threadIdx.x * 32] = 0;
    if (threadIdx.x == 16) g_wmax = 0;
}

__global__ __launch_bounds__(256) void wmax_kernel(const float* __restrict__ Wh) {
    int idx = blockIdx.x * 256 + threadIdx.x;
    float v = fabsf(Wh[idx]);
    #pragma unroll
    for (int o = 16; o; o >>= 1) v = fmaxf(v, __shfl_xor_sync(0xFFFFFFFFu, v, o));
    if ((threadIdx.x & 31) == 0) atomicMax(&g_wmax, __float_as_uint(v));
}

// Wh fp32 [k][n] -> g_Wq[n][k]=j1, g_Wq[n][512+k]=j2
__global__ __launch_bounds__(256) void wquant_kernel(const float* __restrict__ Wh) {
    int idx = blockIdx.x * 256 + threadIdx.x;          // UU*UU
    int n = idx >> 9, k = idx & 511;
    float wmax = __uint_as_float(g_wmax);
    float s1 = wmax * (1.f / 127.f);
    float w = Wh[k * UU + n];
    int j1 = __float2int_rn(__fdividef(w, s1));
    float r = w - (float)j1 * s1;
    int j2 = __float2int_rn(__fdividef(r * 128.f, s1));
    g_Wq[n * HROW + k]       = (int8_t)j1;
    g_Wq[n * HROW + 512 + k] = (int8_t)j2;
}

__global__ __launch_bounds__(256) void xt_kernel(const int* __restrict__ x) {
    int idx = blockIdx.x * 256 + threadIdx.x;          // idx = t*BB + b
    if (idx < TT * BB) {
        int t = idx / BB, b = idx - t * BB;
        g_xT[idx] = x[b * TT + t];
    }
}

// P = emb @ Wx1 + b1
__global__ __launch_bounds__(256) void p_kernel(
    const float* __restrict__ emb, const float* __restrict__ Wx,
    const float* __restrict__ b1)
{
    __shared__ float As[16][64];
    __shared__ float Bs[16][64];
    const int tid = threadIdx.x;
    const int tx = tid & 15, ty = tid >> 4;
    const int row0 = blockIdx.y * 64, col0 = blockIdx.x * 64;
    const int lm = tid >> 2, lkq = tid & 3;
    const int lk = tid >> 4, lnq = tid & 15;
    float acc[4][4] = {};
    for (int k0 = 0; k0 < 112; k0 += 16) {
        int ea = k0 + lkq * 4;
        int ar = row0 + lm;
        float4 av = (ea < EE && ar < VV) ? *(const float4*)&emb[ar * EE + ea]
                                         : make_float4(0.f, 0.f, 0.f, 0.f);
        int eb = k0 + lk;
        float4 bv = (eb < EE) ? *(const float4*)&Wx[eb * UU + col0 + lnq * 4]
                              : make_float4(0.f, 0.f, 0.f, 0.f);
        __syncthreads();
        As[lkq * 4 + 0][lm] = av.x; As[lkq * 4 + 1][lm] = av.y;
        As[lkq * 4 + 2][lm] = av.z; As[lkq * 4 + 3][lm] = av.w;
        *(float4*)&Bs[lk][lnq * 4] = bv;
        __syncthreads();
        #pragma unroll
        for (int k = 0; k < 16; k++) {
            float4 a = *(const float4*)&As[k][ty * 4];
            float4 b = *(const float4*)&Bs[k][tx * 4];
            float ar4[4] = {a.x, a.y, a.z, a.w};
            float br4[4] = {b.x, b.y, b.z, b.w};
            #pragma unroll
            for (int i = 0; i < 4; i++)
                #pragma unroll
                for (int j = 0; j < 4; j++)
                    acc[i][j] += ar4[i] * br4[j];
        }
    }
    #pragma unroll
    for (int i = 0; i < 4; i++) {
        int r = row0 + ty * 4 + i;
        if (r < VV)
            #pragma unroll
            for (int j = 0; j < 4; j++)
                g_P[r * UU + col0 + tx * 4 + j] = acc[i][j] + b1[col0 + tx * 4 + j];
    }
}

// ================= persistent RNN kernel (IMMA s8) =================
// chunk c covers k-bytes [c*128, c*128+128), both levels; stage = c (4 stages)
__device__ __forceinline__ void compute_stage_s8(
    uint32_t aT, uint32_t bB, int c, int warp_m, int warp_n, int lane,
    int acc1[2][4][4], int acc2[2][4][4])
{
    const int g = lane >> 3;
    #pragma unroll
    for (int kf = 0; kf < 4; kf++) {           // 4 k-steps of 32 int8
        // A fragments: [mi][lvl][4]
        uint32_t a_[2][2][4];
        #pragma unroll
        for (int mi = 0; mi < 2; mi++) {
            uint32_t off = sw128((warp_m * 32 + mi * 16 + (g & 1) * 8 + (lane & 7)) * 128
                                 + kf * 32 + (g >> 1) * 16);
            #pragma unroll
            for (int lvl = 0; lvl < 2; lvl++) {
                asm volatile("ldmatrix.sync.aligned.m8n8.x4.shared.b16 {%0,%1,%2,%3}, [%4];"
                    : "=r"(a_[mi][lvl][0]), "=r"(a_[mi][lvl][1]),
                      "=r"(a_[mi][lvl][2]), "=r"(a_[mi][lvl][3])
                    : "r"(aT + lvl * 16384 + off));
            }
        }
        // B fragments: [lvl][ni][2]
        uint32_t b_[2][4][2];
        #pragma unroll
        for (int ni2 = 0; ni2 < 2; ni2++) {
            uint32_t off = sw128((warp_n * 32 + ni2 * 16 + (g >> 1) * 8 + (lane & 7)) * 128
                                 + kf * 32 + (g & 1) * 16);
            #pragma unroll
            for (int lvl = 0; lvl < 2; lvl++) {
                asm volatile("ldmatrix.sync.aligned.m8n8.x4.shared.b16 {%0,%1,%2,%3}, [%4];"
                    : "=r"(b_[lvl][ni2 * 2][0]), "=r"(b_[lvl][ni2 * 2][1]),
                      "=r"(b_[lvl][ni2 * 2 + 1][0]), "=r"(b_[lvl][ni2 * 2 + 1][1])
                    : "r"(bB + (lvl * 4 + c) * 8192 + off));
            }
        }
        #pragma unroll
        for (int mi = 0; mi < 2; mi++)
            #pragma unroll
            for (int ni = 0; ni < 4; ni++) {
                #define IMMA(ACC, AL, BL)                                             \
                    asm volatile(                                                     \
                        "mma.sync.aligned.m16n8k32.row.col.s32.s8.s8.s32 "            \
                        "{%0,%1,%2,%3}, {%4,%5,%6,%7}, {%8,%9}, {%0,%1,%2,%3};"       \
                        : "+r"(ACC[mi][ni][0]), "+r"(ACC[mi][ni][1]),                 \
                          "+r"(ACC[mi][ni][2]), "+r"(ACC[mi][ni][3])                  \
                        : "r"(a_[mi][AL][0]), "r"(a_[mi][AL][1]),                     \
                          "r"(a_[mi][AL][2]), "r"(a_[mi][AL][3]),                     \
                          "r"(b_[BL][ni][0]), "r"(b_[BL][ni][1]))
                IMMA(acc1, 0, 0);   // i1*j1
                IMMA(acc2, 1, 0);   // i2*j1
                IMMA(acc2, 0, 1);   // i1*j2
                #undef IMMA
            }
    }
}

__global__ __launch_bounds__(256, 1) void rnn_kernel(
    const float* __restrict__ Wout, const float* __restrict__ bout,
    float* __restrict__ out)
{
    extern __shared__ char smem[];
    const uint32_t bB = smem_u32(smem) + SM_B;
    const uint32_t aB = smem_u32(smem) + SM_A;

    const int tid  = threadIdx.x;
    const int wid  = tid >> 5;
    const int lane = tid & 31;
    const int warp_m = wid >> 1;
    const int warp_n = wid & 1;
    const int n_tile = blockIdx.x & 7;
    const int m_tile = blockIdx.x >> 3;
    const int N0 = n_tile * NT;
    const int M0 = m_tile * MT;
    unsigned int* const my_bar = &g_bars[m_tile * 32];

    const float wmax = __uint_as_float(g_wmax);
    const float f1 = wmax * (1.f / 16129.f);       // (1/127)*(wmax/127)
    const float f2 = f1 * (1.f / 128.f);

    // ---- load resident B slice once: 8 blocks (lvl*4 + kb) x 8KB ----
    #pragma unroll 4
    for (int i = 0; i < 16; i++) {
        int u = tid + i * 256;           // 4096 16B units
        int blk = u >> 9, rm = u & 511;
        int n = rm >> 3, kg = rm & 7;
        int koff = (blk >> 2) * 512 + (blk & 3) * 128 + kg * 16;
        CP_ASYNC16(bB + blk * 8192 + sw128(n * 128 + kg * 16),
                   g_Wq + (size_t)(N0 + n) * HROW + koff);
    }
    CP_COMMIT(); CP_WAITN(0);
    __syncthreads();

    unsigned int bar_target = 8;

    #define ISSUE_A(c) do {                                                           \
        _Pragma("unroll")                                                             \
        for (int i = 0; i < 4; i++) {                                                 \
            int u = tid + i * 256; int m = u >> 3; int kg = u & 7;                    \
            uint32_t sd = aB + (c) * 32768 + sw128(m * 128 + kg * 16);                \
            const uint8_t* gs = Hsrc + (size_t)(M0 + m) * HROW + (c) * 128 + kg * 16; \
            CP_ASYNC16(sd, gs);                                                       \
            CP_ASYNC16(sd + 16384, gs + 512);                                         \
        }                                                                             \
        CP_COMMIT();                                                                  \
    } while (0)

    const int r = lane >> 2, q = lane & 3;
    const int gmA_base = M0 + warp_m * 32 + r;

    for (int t = 0; t < TT; t++) {
        const int src = t & 1, dst = src ^ 1;
        int acc1[2][4][4] = {};
        int acc2[2][4][4] = {};

        const int* __restrict__ xrow = g_xT + t * BB;
        const int tokA0 = xrow[gmA_base];
        const int tokB0 = xrow[gmA_base + 8];
        const int tokA1 = xrow[gmA_base + 16];
        const int tokB1 = xrow[gmA_base + 24];

        if (t > 0) {
            const uint8_t* __restrict__ Hsrc = g_Hq[src];
            ISSUE_A(0); ISSUE_A(1);
            #pragma unroll
            for (int kb = 0; kb < 4; kb++) {
                if (kb < 3) CP_WAITN(1); else CP_WAITN(0);
                __syncthreads();     // publish everyone's chunk-kb copies
                if (kb <= 1) ISSUE_A(kb + 2);
                compute_stage_s8(aB + kb * 32768, bB, kb, warp_m, warp_n, lane,
                                 acc1, acc2);
            }
        }

        // ---- epilogue: h = tanh(f1*acc1 + f2*acc2 + P[tok]); quantize 2-level ----
        {
            uint8_t* __restrict__ hbase = g_Hq[dst];
            const int toks[2][2] = {{tokA0, tokB0}, {tokA1, tokB1}};
            #pragma unroll
            for (int mi = 0; mi < 2; mi++) {
                const int gmA = gmA_base + mi * 16;
                const int gmB = gmA + 8;
                const float* __restrict__ pA = g_P + (size_t)toks[mi][0] * UU;
                const float* __restrict__ pB = g_P + (size_t)toks[mi][1] * UU;
                uint8_t* __restrict__ dA = hbase + (size_t)gmA * HROW;
                uint8_t* __restrict__ dB = hbase + (size_t)gmB * HROW;
                #pragma unroll
                for (int ni = 0; ni < 4; ni++) {
                    const int gc = N0 + warp_n * 32 + ni * 8 + q * 2;
                    float2 pa = *(const float2*)(pA + gc);
                    float2 pb = *(const float2*)(pB + gc);
                    float h0 = fast_tanh((float)acc1[mi][ni][0] * f1 + (float)acc2[mi][ni][0] * f2 + pa.x);
                    float h1 = fast_tanh((float)acc1[mi][ni][1] * f1 + (float)acc2[mi][ni][1] * f2 + pa.y);
                    float h2 = fast_tanh((float)acc1[mi][ni][2] * f1 + (float)acc2[mi][ni][2] * f2 + pb.x);
                    float h3 = fast_tanh((float)acc1[mi][ni][3] * f1 + (float)acc2[mi][ni][3] * f2 + pb.y);
                    int a1i, a2i, b1i, b2i, c1i, c2i, d1i, d2i;
                    hquant(h0, a1i, a2i); hquant(h1, b1i, b2i);
                    hquant(h2, c1i, c2i); hquant(h3, d1i, d2i);
                    *(unsigned short*)(dA + gc) =
                        (unsigned short)((a1i & 0xFF) | ((b1i & 0xFF) << 8));
                    *(unsigned short*)(dA + 512 + gc) =
                        (unsigned short)((a2i & 0xFF) | ((b2i & 0xFF) << 8));
                    *(unsigned short*)(dB + gc) =
                        (unsigned short)((c1i & 0xFF) | ((d1i & 0xFF) << 8));
                    *(unsigned short*)(dB + 512 + gc) =
                        (unsigned short)((c2i & 0xFF) | ((d2i & 0xFF) << 8));
                }
            }
        }

        gbar_group(my_bar, bar_target);
        bar_target += 8;
    }
    #undef ISSUE_A

    // ---- output phase: rows M0..M0+127, by the 16 CTAs with n_tile==0 ----
    if (n_tile == 0) {
        const uint8_t* __restrict__ hb = g_Hq[0];
        const float bo = bout[0];
        #pragma unroll 4
        for (int rr = 0; rr < 16; rr++) {
            const int gm = M0 + wid * 16 + rr;
            const uint8_t* row = hb + (size_t)gm * HROW;
            float s = 0.f;
            #pragma unroll
            for (int k = lane; k < UU; k += 32) {
                float hv = (float)((int8_t)row[k]) * C_A1
                         + (float)((int8_t)row[512 + k]) * C_A2;
                s += hv * Wout[k];
            }
            #pragma unroll
            for (int o = 16; o; o >>= 1) s += __shfl_xor_sync(0xFFFFFFFFu, s, o);
            if (lane == 0) out[gm] = 1.f / (1.f + expf(-(s + bo)));
        }
    }
}

// ================= launcher =================
extern "C" void kernel_launch(void* const* d_in, const int* in_sizes, int n_in,
                              void* d_out, int out_size)
{
    (void)in_sizes; (void)n_in; (void)out_size;
    const int*   x    = (const int*)  d_in[0];
    const float* emb  = (const float*)d_in[1];
    // Wx0/Wh0/b0 (d_in[2..4]) are dead code in the reference.
    const float* Wx1  = (const float*)d_in[5];
    const float* Wh1  = (const float*)d_in[6];
    const float* b1   = (const float*)d_in[7];
    const float* Wout = (const float*)d_in[8];
    const float* bout = (const float*)d_in[9];
    float* out = (float*)d_out;

    cudaFuncSetAttribute(rnn_kernel, cudaFuncAttributeMaxDynamicSharedMemorySize, SM_TOT);

    reset_kernel<<<1, 32>>>();
    wmax_kernel<<<UU * UU / 256, 256>>>(Wh1);
    wquant_kernel<<<UU * UU / 256, 256>>>(Wh1);
    xt_kernel<<<(TT * BB + 255) / 256, 256>>>(x);
    p_kernel<<<dim3(8, 157), 256>>>(emb, Wx1, b1);
    rnn_kernel<<<NCTA, 256, SM_TOT>>>(Wout, bout, out);
}